// round 1
// baseline (speedup 1.0000x reference)
#include <cuda_runtime.h>

#define BATCH_ 131072
#define DD 784
#define HID 256
#define MD 16

// Scratch (device globals; no allocation allowed in kernel_launch)
__device__ float g_h [(size_t)BATCH_ * HID];   // relu(x@W1+b1)
__device__ float g_gf[(size_t)BATCH_ * HID];   // h@W2+b2
__device__ float g_xi[(size_t)BATCH_ * MD];    // x@Wp+bp

// ---------------------------------------------------------------------------
// Classic 128x128x8 register-blocked SGEMM: C = op(A[M,K] @ W[K,N] + bias[N])
// 256 threads, each computes an 8x8 tile. RELU applied when template flag set.
// ---------------------------------------------------------------------------
template <int RELU>
__global__ __launch_bounds__(256)
void sgemm128(const float* __restrict__ A, const float* __restrict__ W,
              const float* __restrict__ bias, float* __restrict__ C,
              int M, int N, int K)
{
    __shared__ float As[8][128];
    __shared__ float Bs[8][128];

    const int tid = threadIdx.x;
    const int tx  = tid & 15;        // 0..15 -> 8 output cols each
    const int ty  = tid >> 4;        // 0..15 -> 8 output rows each
    const size_t br = blockIdx.y;    // M / 128
    const size_t bc = blockIdx.x;    // N / 128

    const float* Ab = A + br * 128 * (size_t)K;
    const float* Wb = W + bc * 128;

    float acc[8][8];
#pragma unroll
    for (int i = 0; i < 8; i++)
#pragma unroll
        for (int j = 0; j < 8; j++) acc[i][j] = 0.0f;

    const int arow = tid >> 1;           // 0..127
    const int ac4  = (tid & 1) * 4;      // 0 or 4
    const int brow = tid >> 5;           // 0..7
    const int bc4  = (tid & 31) * 4;     // 0..124

    for (int kt = 0; kt < K; kt += 8) {
        float4 av = *(const float4*)(Ab + (size_t)arow * K + kt + ac4);
        As[ac4 + 0][arow] = av.x;
        As[ac4 + 1][arow] = av.y;
        As[ac4 + 2][arow] = av.z;
        As[ac4 + 3][arow] = av.w;
        float4 bv = *(const float4*)(Wb + (size_t)(kt + brow) * N + bc4);
        *(float4*)&Bs[brow][bc4] = bv;
        __syncthreads();

#pragma unroll
        for (int k = 0; k < 8; k++) {
            float ar[8], bw[8];
#pragma unroll
            for (int i = 0; i < 8; i++) ar[i] = As[k][ty * 8 + i];
#pragma unroll
            for (int j = 0; j < 8; j++) bw[j] = Bs[k][tx * 8 + j];
#pragma unroll
            for (int i = 0; i < 8; i++)
#pragma unroll
                for (int j = 0; j < 8; j++) acc[i][j] += ar[i] * bw[j];
        }
        __syncthreads();
    }

    float bcol[8];
#pragma unroll
    for (int j = 0; j < 8; j++) bcol[j] = bias[bc * 128 + tx * 8 + j];

#pragma unroll
    for (int i = 0; i < 8; i++) {
        const size_t row = br * 128 + ty * 8 + i;
        float* Crow = C + row * (size_t)N + bc * 128 + tx * 8;
        float4 v0, v1;
        float tmp[8];
#pragma unroll
        for (int j = 0; j < 8; j++) {
            float v = acc[i][j] + bcol[j];
            if (RELU) v = v > 0.0f ? v : 0.0f;
            tmp[j] = v;
        }
        v0.x = tmp[0]; v0.y = tmp[1]; v0.z = tmp[2]; v0.w = tmp[3];
        v1.x = tmp[4]; v1.y = tmp[5]; v1.z = tmp[6]; v1.w = tmp[7];
        *(float4*)(Crow + 0) = v0;
        *(float4*)(Crow + 4) = v1;
    }
}

// ---------------------------------------------------------------------------
// xi = x @ Wp + bp   (B x 784 @ 784 x 16). One warp per row.
// ---------------------------------------------------------------------------
__global__ __launch_bounds__(256)
void xi_kernel(const float* __restrict__ x, const float* __restrict__ Wp,
               const float* __restrict__ bp, float* __restrict__ xiout)
{
    const int w = threadIdx.x >> 5, lane = threadIdx.x & 31;
    const size_t row = (size_t)blockIdx.x * 8 + w;
    const float* xr = x + row * DD;

    float acc[MD];
#pragma unroll
    for (int j = 0; j < MD; j++) acc[j] = 0.0f;

    for (int k = lane; k < DD; k += 32) {
        const float xv = xr[k];
        const float* wr = Wp + (size_t)k * MD;
#pragma unroll
        for (int j = 0; j < MD; j++) acc[j] += xv * __ldg(wr + j);
    }
#pragma unroll
    for (int j = 0; j < MD; j++) {
#pragma unroll
        for (int off = 16; off > 0; off >>= 1)
            acc[j] += __shfl_xor_sync(0xffffffffu, acc[j], off);
    }
    if (lane < MD) xiout[row * MD + lane] = acc[lane] + bp[lane];
}

// ---------------------------------------------------------------------------
// Per-row: A = reshape(gf, 16x16); g = A A^T + 0.1 I; solve g y = -xi/(t+eps);
// out = y @ Wl + bl.   One warp per row, 8 rows per block.
// Direct SPD solve (Gaussian elimination, no pivoting) replaces linalg.inv.
// ---------------------------------------------------------------------------
__global__ __launch_bounds__(256)
void solve_out_kernel(const float* __restrict__ gf, const float* __restrict__ xi,
                      const float* __restrict__ t,
                      const float* __restrict__ Wl, const float* __restrict__ bl,
                      float* __restrict__ out)
{
    __shared__ float Am[8][MD][MD];
    __shared__ float G [8][MD][MD + 1];
    __shared__ float Y [8][MD];

    const int w = threadIdx.x >> 5, lane = threadIdx.x & 31;
    const size_t row = (size_t)blockIdx.x * 8 + w;

    // Load A (coalesced)
    const float* gfr = gf + row * HID;
    for (int k = lane; k < HID; k += 32) Am[w][k >> 4][k & 15] = gfr[k];
    if (lane < MD) {
        const float tv = t[row] + 1e-6f;
        Y[w][lane] = -xi[row * MD + lane] / tv;
    }
    __syncwarp();

    // g = A A^T + 0.1 I  (each lane computes 8 of the 256 entries)
    for (int p = lane; p < MD * MD; p += 32) {
        const int i = p >> 4, j = p & 15;
        float s = (i == j) ? 0.1f : 0.0f;
#pragma unroll
        for (int k = 0; k < MD; k++) s += Am[w][i][k] * Am[w][j][k];
        G[w][i][j] = s;
    }
    __syncwarp();

    // Forward elimination (SPD, no pivoting). Row-per-lane for rows i > k.
    for (int k = 0; k < MD; k++) {
        const float piv = G[w][k][k];
        const int i = k + 1 + lane;
        if (i < MD) {
            const float f = G[w][i][k] / piv;
            for (int c = k; c < MD; c++) G[w][i][c] -= f * G[w][k][c];
            Y[w][i] -= f * Y[w][k];
        }
        __syncwarp();
    }
    // Back substitution (tiny; lane 0)
    if (lane == 0) {
        for (int k = MD - 1; k >= 0; k--) {
            float s = Y[w][k];
            for (int c = k + 1; c < MD; c++) s -= G[w][k][c] * Y[w][c];
            Y[w][k] = s / G[w][k][k];
        }
    }
    __syncwarp();

    float yr[MD];
#pragma unroll
    for (int k = 0; k < MD; k++) yr[k] = Y[w][k];

    // out = y @ Wl + bl  (coalesced across lanes; Wl is 50KB -> L2-resident)
    float* orow = out + row * DD;
    for (int o = lane; o < DD; o += 32) {
        float s = __ldg(bl + o);
#pragma unroll
        for (int k = 0; k < MD; k++) s += yr[k] * __ldg(Wl + (size_t)k * DD + o);
        orow[o] = s;
    }
}

// ---------------------------------------------------------------------------
extern "C" void kernel_launch(void* const* d_in, const int* in_sizes, int n_in,
                              void* d_out, int out_size)
{
    const float* x_t = (const float*)d_in[0];
    const float* t   = (const float*)d_in[1];
    const float* W1  = (const float*)d_in[2];
    const float* b1  = (const float*)d_in[3];
    const float* W2  = (const float*)d_in[4];
    const float* b2  = (const float*)d_in[5];
    const float* Wp  = (const float*)d_in[6];
    const float* bp  = (const float*)d_in[7];
    const float* Wl  = (const float*)d_in[8];
    const float* bl  = (const float*)d_in[9];
    float* out = (float*)d_out;

    float *hptr, *gfptr, *xiptr;
    cudaGetSymbolAddress((void**)&hptr,  g_h);
    cudaGetSymbolAddress((void**)&gfptr, g_gf);
    cudaGetSymbolAddress((void**)&xiptr, g_xi);

    // xi = x @ Wp + bp
    xi_kernel<<<BATCH_ / 8, 256>>>(x_t, Wp, bp, xiptr);

    // h = relu(x @ W1 + b1)
    {
        dim3 grid(HID / 128, BATCH_ / 128);
        sgemm128<1><<<grid, 256>>>(x_t, W1, b1, hptr, BATCH_, HID, DD);
    }
    // gf = h @ W2 + b2
    {
        dim3 grid(HID / 128, BATCH_ / 128);
        sgemm128<0><<<grid, 256>>>(hptr, W2, b2, gfptr, BATCH_, HID, HID);
    }
    // build g, solve, project to data space
    solve_out_kernel<<<BATCH_ / 8, 256>>>(gfptr, xiptr, t, Wl, bl, out);
}